// round 14
// baseline (speedup 1.0000x reference)
#include <cuda_runtime.h>
#include <cuda_fp16.h>
#include <cstdint>

// ---------------- problem constants ----------------
#define NSAMP  15552
#define NJ     17
#define MROWS  (NSAMP*NJ)        // 264384
#define MTILES 2066              // ceil(MROWS/128)
#define MPAD   (MTILES*128)      // 264448
#define DIN    256
#define DOUT   256
#define DMID   512
#define EPSV   1e-5f

// ---------------- scratch (device globals; no runtime alloc) ----------------
static __device__ __half g_xah  [(size_t)MPAD * DIN];
static __device__ float  g_h    [(size_t)MPAD * DOUT];   // post-GCN relu h (fp32)
static __device__ __half g_hnh  [(size_t)MPAD * DOUT];   // BN+LN output (fp16)
static __device__ __half g_midh [(size_t)MPAD * DMID];

static __device__ __half g_wh   [DOUT * DIN];
static __device__ __half g_mw1h [DMID * DOUT];
static __device__ __half g_mw2h [DOUT * DMID];

static __device__ float g_bias [DOUT];
static __device__ float g_rs   [NJ];
static __device__ float g_bnsum[DOUT];
static __device__ float g_bnsq [DOUT];
static __device__ float g_scale[DOUT];
static __device__ float g_shift[DOUT];

// ---------------- helpers ----------------
__device__ __forceinline__ uint32_t smem_u32(const void* p) {
    uint32_t a;
    asm("{ .reg .u64 t; cvta.to.shared.u64 t, %1; cvt.u32.u64 %0, t; }" : "=r"(a) : "l"(p));
    return a;
}
__device__ __forceinline__ void ldsm4(uint32_t* r, uint32_t addr) {
    asm volatile("ldmatrix.sync.aligned.m8n8.x4.shared.b16 {%0,%1,%2,%3}, [%4];"
                 : "=r"(r[0]), "=r"(r[1]), "=r"(r[2]), "=r"(r[3]) : "r"(addr));
}
__device__ __forceinline__ void mma_fp(float* c, const uint32_t* a, uint32_t b0, uint32_t b1) {
    asm volatile("mma.sync.aligned.m16n8k16.row.col.f32.f16.f16.f32 "
                 "{%0,%1,%2,%3}, {%4,%5,%6,%7}, {%8,%9}, {%0,%1,%2,%3};"
                 : "+f"(c[0]), "+f"(c[1]), "+f"(c[2]), "+f"(c[3])
                 : "r"(a[0]), "r"(a[1]), "r"(a[2]), "r"(a[3]), "r"(b0), "r"(b1));
}
__device__ __forceinline__ void cpa16(uint32_t dst, const void* src) {
    asm volatile("cp.async.cg.shared.global [%0], [%1], 16;" :: "r"(dst), "l"(src));
}
#define CP_COMMIT() asm volatile("cp.async.commit_group;" ::: "memory")
#define CP_WAIT0()  asm volatile("cp.async.wait_group 0;" ::: "memory")

__device__ __forceinline__ uint32_t pack_half2(float a, float b) {
    __half2 h = __floats2half2_rn(a, b);
    return *(uint32_t*)&h;
}

// ---------------- K0: prep (weights->fp16, bias, rowsums, BN zero, pad zero) ----------------
__global__ void prep_kernel(const float* __restrict__ w1, const float* __restrict__ b1,
                            const float* __restrict__ w2, const float* __restrict__ b2,
                            const float* __restrict__ adj,
                            const float* __restrict__ mw1, const float* __restrict__ mw2) {
    int bid = blockIdx.x, tid = threadIdx.x;
    if (bid < 256) {
        int i = bid * 256 + tid;
        g_wh[i] = __float2half_rn(w1[i] + w2[i]);
    } else if (bid < 768) {
        int i = (bid - 256) * 256 + tid;
        g_mw1h[i] = __float2half_rn(mw1[i]);
    } else {
        int i = (bid - 768) * 256 + tid;
        g_mw2h[i] = __float2half_rn(mw2[i]);
    }
    if (bid < 64) {
        // zero padded tail rows of xa and hn (64 rows x 256 each)
        size_t p = (size_t)MROWS * 256 + bid * 256 + tid;
        g_xah[p] = __float2half(0.0f);
        g_hnh[p] = __float2half(0.0f);
    }
    if (bid == 0) {
        g_bias[tid]  = b1[tid] + b2[tid];
        g_bnsum[tid] = 0.0f;
        g_bnsq[tid]  = 0.0f;
        if (tid < NJ) {
            float s = 0.0f;
            #pragma unroll
            for (int j = 0; j < NJ; j++) s += adj[tid * NJ + j];
            g_rs[tid] = s;
        }
    }
}

// ---------------- K1: adjacency aggregation -> fp16 ----------------
__global__ void agg_kernel(const float* __restrict__ x, const float* __restrict__ adj) {
    __shared__ float sadj[NJ * NJ];
    int t = threadIdx.x;
    for (int i = t; i < NJ * NJ; i += 256) sadj[i] = adj[i];
    __syncthreads();
    size_t base = (size_t)blockIdx.x * NJ * DIN + t;
    const float* xs = x + base;
    float xv[NJ];
    #pragma unroll
    for (int j = 0; j < NJ; j++) xv[j] = xs[(size_t)j * DIN];
    #pragma unroll
    for (int i = 0; i < NJ; i++) {
        float a = 0.0f;
        #pragma unroll
        for (int j = 0; j < NJ; j++) a = fmaf(sadj[i * NJ + j], xv[j], a);
        g_xah[base + (size_t)i * DIN] = __float2half_rn(a);
    }
}

// ---------------- unified fp16 HMMA GEMM ----------------
// Block 128x128, BK=64, 8 warps (2M x 4N), warp tile 64x32. 32 KB smem.
// MODE 0: h(fp32) = relu(xa @ w^T + rs*bias) + fused BN stats
// MODE 1: mid = relu(hn @ mw1^T + b1)    (half out)
// MODE 2: out = mid @ mw2^T + b2         (fp32 out, row-guarded)
template<int K, int MODE>
__global__ void __launch_bounds__(256, 2)
mma_gemm_h(const float* __restrict__ biasx, float* __restrict__ Cout) {
    extern __shared__ char smem[];
    const uint32_t sb = smem_u32(smem);
    constexpr uint32_t BOF = 16384;

    int tid = threadIdx.x;
    int wid = tid >> 5, lane = tid & 31;
    int wm0 = (wid & 1) * 64;
    int wn0 = (wid >> 1) * 32;

    size_t m0 = (size_t)blockIdx.y * 128;
    int    n0 = blockIdx.x * 128;

    const __half* A = (MODE == 0) ? g_xah : ((MODE == 1) ? g_hnh  : g_midh);
    const __half* B = (MODE == 0) ? g_wh  : ((MODE == 1) ? g_mw1h : g_mw2h);

    float acc[4][4][4] = {};

    int la = lane & 15, lb = lane >> 4;
    int swA = la & 7;
    uint32_t aBase = sb + (uint32_t)(wm0 + la) * 128u;
    uint32_t browB = (uint32_t)(wn0 + (lane & 7) + ((lane >> 4) << 3));
    int bCk = (lane >> 3) & 1;
    int swB = lane & 7;
    uint32_t bBase = sb + BOF + browB * 128u;

    int srr = tid >> 3, scc = tid & 7;

    #pragma unroll
    for (int kc = 0; kc < K / 64; kc++) {
        #pragma unroll
        for (int q = 0; q < 4; q++) {
            int r = srr + q * 32;
            size_t goA = (m0 + r) * (size_t)K + kc * 64 + scc * 8;
            size_t goB = (size_t)(n0 + r) * K + kc * 64 + scc * 8;
            uint32_t so = (uint32_t)(r * 128 + ((scc ^ (r & 7)) << 4));
            cpa16(sb + so, A + goA);
            cpa16(sb + BOF + so, B + goB);
        }
        CP_COMMIT();
        CP_WAIT0();
        __syncthreads();

        #pragma unroll
        for (int ks = 0; ks < 4; ks++) {
            int ca = ks * 2 + lb;
            int cb = ks * 2 + bCk;
            uint32_t choA = (uint32_t)((ca ^ swA) << 4);
            uint32_t choB = (uint32_t)((cb ^ swB) << 4);
            uint32_t ah[4][4];
            uint32_t bh0[4], bh1[4];
            #pragma unroll
            for (int mf = 0; mf < 4; mf++)
                ldsm4(ah[mf], aBase + mf * 2048u + choA);
            ldsm4(bh0, bBase + choB);
            ldsm4(bh1, bBase + 2048u + choB);
            #pragma unroll
            for (int mf = 0; mf < 4; mf++) {
                #pragma unroll
                for (int nf = 0; nf < 4; nf++) {
                    const uint32_t* BHf = (nf < 2) ? bh0 : bh1;
                    uint32_t b0 = BHf[(nf & 1) * 2], b1 = BHf[(nf & 1) * 2 + 1];
                    mma_fp(acc[mf][nf], ah[mf], b0, b1);
                }
            }
        }
        __syncthreads();
    }

    int colq = 2 * (lane & 3);
    int rowq = lane >> 2;

    if (MODE == 0) {
        // rs*bias + relu -> fp32 h; fused BN stats
        float* sstat = (float*)smem;
        sstat[tid] = 0.0f;
        __syncthreads();

        float lsum[8], lsq[8];
        #pragma unroll
        for (int j = 0; j < 8; j++) { lsum[j] = 0.0f; lsq[j] = 0.0f; }
        #pragma unroll
        for (int mf = 0; mf < 4; mf++) {
            size_t r0 = m0 + wm0 + mf * 16 + rowq;
            size_t r1 = r0 + 8;
            float rs0 = g_rs[(int)(r0 % NJ)];
            float rs1 = g_rs[(int)(r1 % NJ)];
            bool v0 = r0 < MROWS, v1 = r1 < MROWS;
            #pragma unroll
            for (int nf = 0; nf < 4; nf++) {
                int c = n0 + wn0 + nf * 8 + colq;
                float b0 = g_bias[c], b1 = g_bias[c + 1];
                float x0 = fmaxf(acc[mf][nf][0] + rs0 * b0, 0.0f);
                float x1 = fmaxf(acc[mf][nf][1] + rs0 * b1, 0.0f);
                float x2 = fmaxf(acc[mf][nf][2] + rs1 * b0, 0.0f);
                float x3 = fmaxf(acc[mf][nf][3] + rs1 * b1, 0.0f);
                *(float2*)(g_h + r0 * DOUT + c) = make_float2(x0, x1);
                *(float2*)(g_h + r1 * DOUT + c) = make_float2(x2, x3);
                if (v0) {
                    lsum[nf*2]   += x0; lsq[nf*2]   = fmaf(x0, x0, lsq[nf*2]);
                    lsum[nf*2+1] += x1; lsq[nf*2+1] = fmaf(x1, x1, lsq[nf*2+1]);
                }
                if (v1) {
                    lsum[nf*2]   += x2; lsq[nf*2]   = fmaf(x2, x2, lsq[nf*2]);
                    lsum[nf*2+1] += x3; lsq[nf*2+1] = fmaf(x3, x3, lsq[nf*2+1]);
                }
            }
        }
        #pragma unroll
        for (int o = 4; o < 32; o <<= 1) {
            #pragma unroll
            for (int j = 0; j < 8; j++) {
                lsum[j] += __shfl_xor_sync(0xffffffffu, lsum[j], o);
                lsq[j]  += __shfl_xor_sync(0xffffffffu, lsq[j],  o);
            }
        }
        if (lane < 4) {
            #pragma unroll
            for (int nf = 0; nf < 4; nf++) {
                #pragma unroll
                for (int j = 0; j < 2; j++) {
                    int cb = wn0 + nf * 8 + 2 * lane + j;
                    atomicAdd(&sstat[cb],       lsum[nf*2 + j]);
                    atomicAdd(&sstat[128 + cb], lsq[nf*2 + j]);
                }
            }
        }
        __syncthreads();
        if (tid < 128) atomicAdd(&g_bnsum[n0 + tid], sstat[tid]);
        else           atomicAdd(&g_bnsq [n0 + tid - 128], sstat[tid]);
    } else if (MODE == 1) {
        #pragma unroll
        for (int mf = 0; mf < 4; mf++) {
            size_t r0 = m0 + wm0 + mf * 16 + rowq;
            size_t r1 = r0 + 8;
            #pragma unroll
            for (int nf = 0; nf < 4; nf++) {
                int c = n0 + wn0 + nf * 8 + colq;
                float b0 = biasx[c], b1 = biasx[c + 1];
                float x0 = fmaxf(acc[mf][nf][0] + b0, 0.0f);
                float x1 = fmaxf(acc[mf][nf][1] + b1, 0.0f);
                float x2 = fmaxf(acc[mf][nf][2] + b0, 0.0f);
                float x3 = fmaxf(acc[mf][nf][3] + b1, 0.0f);
                *(uint32_t*)(g_midh + r0 * DMID + c) = pack_half2(x0, x1);
                *(uint32_t*)(g_midh + r1 * DMID + c) = pack_half2(x2, x3);
            }
        }
    } else {
        #pragma unroll
        for (int mf = 0; mf < 4; mf++) {
            size_t r0 = m0 + wm0 + mf * 16 + rowq;
            size_t r1 = r0 + 8;
            #pragma unroll
            for (int nf = 0; nf < 4; nf++) {
                int c = n0 + wn0 + nf * 8 + colq;
                float b0 = biasx[c], b1 = biasx[c + 1];
                if (r0 < MROWS)
                    *(float2*)(Cout + r0 * DOUT + c) =
                        make_float2(acc[mf][nf][0] + b0, acc[mf][nf][1] + b1);
                if (r1 < MROWS)
                    *(float2*)(Cout + r1 * DOUT + c) =
                        make_float2(acc[mf][nf][2] + b0, acc[mf][nf][3] + b1);
            }
        }
    }
}

// ---------------- BN finalize ----------------
__global__ void bnfin_kernel(const float* __restrict__ bng, const float* __restrict__ bnb) {
    int c = threadIdx.x;
    const float inv = 1.0f / (float)MROWS;
    float mean = g_bnsum[c] * inv;
    float var  = g_bnsq[c] * inv - mean * mean;
    float sc   = bng[c] * rsqrtf(var + EPSV);
    g_scale[c] = sc;
    g_shift[c] = bnb[c] - mean * sc;
}

// ---------------- fused BN + LayerNorm: fp32 h -> fp16 hn (vectorized) ----------------
// 8 warps/block, 1 row/warp; lane owns 8 contiguous channels.
__global__ void bnln_kernel(const float* __restrict__ lng, const float* __restrict__ lnb) {
    int warp = threadIdx.x >> 5, lane = threadIdx.x & 31;
    size_t row = (size_t)blockIdx.x * 8 + warp;
    int c0 = lane * 8;

    const float* hr = g_h + row * DOUT + c0;
    float4 v0 = *(const float4*)(hr);
    float4 v1 = *(const float4*)(hr + 4);
    float vin[8] = {v0.x, v0.y, v0.z, v0.w, v1.x, v1.y, v1.z, v1.w};

    float vals[8];
    float s = 0.0f, sq = 0.0f;
    #pragma unroll
    for (int j = 0; j < 8; j++) {
        float a = fmaf(vin[j], g_scale[c0 + j], g_shift[c0 + j]);
        vals[j] = a;
        s += a;
        sq = fmaf(a, a, sq);
    }
    #pragma unroll
    for (int o = 16; o > 0; o >>= 1) {
        s  += __shfl_xor_sync(0xffffffffu, s,  o);
        sq += __shfl_xor_sync(0xffffffffu, sq, o);
    }
    float mu  = s * (1.0f / DOUT);
    float var = sq * (1.0f / DOUT) - mu * mu;
    float inv = rsqrtf(var + EPSV);

    uint4 w;
    uint32_t* wp = (uint32_t*)&w;
    #pragma unroll
    for (int j = 0; j < 4; j++) {
        float a0 = fmaf((vals[2*j]   - mu) * inv, lng[c0 + 2*j],   lnb[c0 + 2*j]);
        float a1 = fmaf((vals[2*j+1] - mu) * inv, lng[c0 + 2*j+1], lnb[c0 + 2*j+1]);
        wp[j] = pack_half2(a0, a1);
    }
    *(uint4*)(g_hnh + row * DOUT + c0) = w;
}

// ---------------------------------------------------------------------------
extern "C" void kernel_launch(void* const* d_in, const int* in_sizes, int n_in,
                              void* d_out, int out_size) {
    const float* x   = (const float*)d_in[0];
    const float* adj = (const float*)d_in[1];
    const float* w1  = (const float*)d_in[2];
    const float* b1  = (const float*)d_in[3];
    const float* w2  = (const float*)d_in[4];
    const float* b2  = (const float*)d_in[5];
    const float* bng = (const float*)d_in[6];
    const float* bnb = (const float*)d_in[7];
    const float* lng = (const float*)d_in[8];
    const float* lnb = (const float*)d_in[9];
    const float* mw1 = (const float*)d_in[10];
    const float* mb1 = (const float*)d_in[11];
    const float* mw2 = (const float*)d_in[12];
    const float* mb2 = (const float*)d_in[13];
    float* out = (float*)d_out;

    const int SMEMH = 32768;   // 32 KB dynamic (within default limit)

    prep_kernel<<<1280, 256>>>(w1, b1, w2, b2, adj, mw1, mw2);
    agg_kernel<<<NSAMP, 256>>>(x, adj);
    // GEMM1: h(fp32) = relu(xa @ (w1+w2)^T + rs*bias), fused BN stats
    mma_gemm_h<256, 0><<<dim3(2, MTILES), 256, SMEMH>>>(nullptr, nullptr);
    bnfin_kernel<<<1, DOUT>>>(bng, bnb);
    bnln_kernel<<<MROWS / 8, 256>>>(lng, lnb);
    // GEMM2: mid = relu(hn @ mlp_w1^T + mlp_b1)
    mma_gemm_h<256, 1><<<dim3(4, MTILES), 256, SMEMH>>>(mb1, nullptr);
    // GEMM3: out = mid @ mlp_w2^T + mlp_b2
    mma_gemm_h<512, 2><<<dim3(2, MTILES), 256, SMEMH>>>(mb2, out);
}

// round 15
// speedup vs baseline: 1.0475x; 1.0475x over previous
#include <cuda_runtime.h>
#include <cuda_fp16.h>
#include <cstdint>

// ---------------- problem constants ----------------
#define NSAMP  15552
#define NJ     17
#define MROWS  (NSAMP*NJ)        // 264384
#define MTILES 2066              // ceil(MROWS/128)
#define MPAD   (MTILES*128)      // 264448
#define DIN    256
#define DOUT   256
#define DMID   512
#define EPSV   1e-5f

// ---------------- scratch (device globals; no runtime alloc) ----------------
static __device__ __half g_xah  [(size_t)MPAD * DIN];
static __device__ float  g_h    [(size_t)MPAD * DOUT];   // post-GCN relu h (fp32)
static __device__ __half g_hnh  [(size_t)MPAD * DOUT];   // BN+LN output (fp16)

static __device__ __half g_wh   [DOUT * DIN];
static __device__ __half g_mw1h [DMID * DOUT];
static __device__ __half g_mw2h [DOUT * DMID];

static __device__ float g_bias [DOUT];
static __device__ float g_rs   [NJ];
static __device__ float g_bnsum[DOUT];
static __device__ float g_bnsq [DOUT];
static __device__ float g_scale[DOUT];
static __device__ float g_shift[DOUT];

// ---------------- helpers ----------------
__device__ __forceinline__ uint32_t smem_u32(const void* p) {
    uint32_t a;
    asm("{ .reg .u64 t; cvta.to.shared.u64 t, %1; cvt.u32.u64 %0, t; }" : "=r"(a) : "l"(p));
    return a;
}
__device__ __forceinline__ void ldsm4(uint32_t* r, uint32_t addr) {
    asm volatile("ldmatrix.sync.aligned.m8n8.x4.shared.b16 {%0,%1,%2,%3}, [%4];"
                 : "=r"(r[0]), "=r"(r[1]), "=r"(r[2]), "=r"(r[3]) : "r"(addr));
}
__device__ __forceinline__ void mma_fp(float* c, const uint32_t* a, uint32_t b0, uint32_t b1) {
    asm volatile("mma.sync.aligned.m16n8k16.row.col.f32.f16.f16.f32 "
                 "{%0,%1,%2,%3}, {%4,%5,%6,%7}, {%8,%9}, {%0,%1,%2,%3};"
                 : "+f"(c[0]), "+f"(c[1]), "+f"(c[2]), "+f"(c[3])
                 : "r"(a[0]), "r"(a[1]), "r"(a[2]), "r"(a[3]), "r"(b0), "r"(b1));
}
__device__ __forceinline__ void cpa16(uint32_t dst, const void* src) {
    asm volatile("cp.async.cg.shared.global [%0], [%1], 16;" :: "r"(dst), "l"(src));
}
#define CP_COMMIT() asm volatile("cp.async.commit_group;" ::: "memory")
#define CP_WAIT0()  asm volatile("cp.async.wait_group 0;" ::: "memory")

__device__ __forceinline__ uint32_t pack_half2(float a, float b) {
    __half2 h = __floats2half2_rn(a, b);
    return *(uint32_t*)&h;
}

// ---------------- K0: prep ----------------
__global__ void prep_kernel(const float* __restrict__ w1, const float* __restrict__ b1,
                            const float* __restrict__ w2, const float* __restrict__ b2,
                            const float* __restrict__ adj,
                            const float* __restrict__ mw1, const float* __restrict__ mw2) {
    int bid = blockIdx.x, tid = threadIdx.x;
    if (bid < 256) {
        int i = bid * 256 + tid;
        g_wh[i] = __float2half_rn(w1[i] + w2[i]);
    } else if (bid < 768) {
        int i = (bid - 256) * 256 + tid;
        g_mw1h[i] = __float2half_rn(mw1[i]);
    } else {
        int i = (bid - 768) * 256 + tid;
        g_mw2h[i] = __float2half_rn(mw2[i]);
    }
    if (bid < 64) {
        size_t p = (size_t)MROWS * 256 + bid * 256 + tid;
        g_xah[p] = __float2half(0.0f);
        g_hnh[p] = __float2half(0.0f);
    }
    if (bid == 0) {
        g_bias[tid]  = b1[tid] + b2[tid];
        g_bnsum[tid] = 0.0f;
        g_bnsq[tid]  = 0.0f;
        if (tid < NJ) {
            float s = 0.0f;
            #pragma unroll
            for (int j = 0; j < NJ; j++) s += adj[tid * NJ + j];
            g_rs[tid] = s;
        }
    }
}

// ---------------- K1: adjacency aggregation -> fp16 ----------------
__global__ void agg_kernel(const float* __restrict__ x, const float* __restrict__ adj) {
    __shared__ float sadj[NJ * NJ];
    int t = threadIdx.x;
    for (int i = t; i < NJ * NJ; i += 256) sadj[i] = adj[i];
    __syncthreads();
    size_t base = (size_t)blockIdx.x * NJ * DIN + t;
    const float* xs = x + base;
    float xv[NJ];
    #pragma unroll
    for (int j = 0; j < NJ; j++) xv[j] = xs[(size_t)j * DIN];
    #pragma unroll
    for (int i = 0; i < NJ; i++) {
        float a = 0.0f;
        #pragma unroll
        for (int j = 0; j < NJ; j++) a = fmaf(sadj[i * NJ + j], xv[j], a);
        g_xah[base + (size_t)i * DIN] = __float2half_rn(a);
    }
}

// ---------------- GEMM1: fp16 HMMA, h(fp32) + fused BN stats ----------------
// Block 128x128, BK=64, 8 warps (2M x 4N), warp tile 64x32. 32 KB smem.
__global__ void __launch_bounds__(256, 2)
mma_gemm1() {
    extern __shared__ char smem[];
    const uint32_t sb = smem_u32(smem);
    constexpr uint32_t BOF = 16384;
    constexpr int K = DIN;

    int tid = threadIdx.x;
    int wid = tid >> 5, lane = tid & 31;
    int wm0 = (wid & 1) * 64;
    int wn0 = (wid >> 1) * 32;

    size_t m0 = (size_t)blockIdx.y * 128;
    int    n0 = blockIdx.x * 128;

    float acc[4][4][4] = {};

    int la = lane & 15, lb = lane >> 4;
    int swA = la & 7;
    uint32_t aBase = sb + (uint32_t)(wm0 + la) * 128u;
    uint32_t browB = (uint32_t)(wn0 + (lane & 7) + ((lane >> 4) << 3));
    int bCk = (lane >> 3) & 1;
    int swB = lane & 7;
    uint32_t bBase = sb + BOF + browB * 128u;

    int srr = tid >> 3, scc = tid & 7;

    #pragma unroll
    for (int kc = 0; kc < K / 64; kc++) {
        #pragma unroll
        for (int q = 0; q < 4; q++) {
            int r = srr + q * 32;
            size_t goA = (m0 + r) * (size_t)K + kc * 64 + scc * 8;
            size_t goB = (size_t)(n0 + r) * K + kc * 64 + scc * 8;
            uint32_t so = (uint32_t)(r * 128 + ((scc ^ (r & 7)) << 4));
            cpa16(sb + so, g_xah + goA);
            cpa16(sb + BOF + so, g_wh + goB);
        }
        CP_COMMIT();
        CP_WAIT0();
        __syncthreads();

        #pragma unroll
        for (int ks = 0; ks < 4; ks++) {
            int ca = ks * 2 + lb;
            int cb = ks * 2 + bCk;
            uint32_t choA = (uint32_t)((ca ^ swA) << 4);
            uint32_t choB = (uint32_t)((cb ^ swB) << 4);
            uint32_t ah[4][4];
            uint32_t bh0[4], bh1[4];
            #pragma unroll
            for (int mf = 0; mf < 4; mf++)
                ldsm4(ah[mf], aBase + mf * 2048u + choA);
            ldsm4(bh0, bBase + choB);
            ldsm4(bh1, bBase + 2048u + choB);
            #pragma unroll
            for (int mf = 0; mf < 4; mf++) {
                #pragma unroll
                for (int nf = 0; nf < 4; nf++) {
                    const uint32_t* BHf = (nf < 2) ? bh0 : bh1;
                    uint32_t b0 = BHf[(nf & 1) * 2], b1 = BHf[(nf & 1) * 2 + 1];
                    mma_fp(acc[mf][nf], ah[mf], b0, b1);
                }
            }
        }
        __syncthreads();
    }

    int colq = 2 * (lane & 3);
    int rowq = lane >> 2;

    float* sstat = (float*)smem;
    sstat[tid] = 0.0f;
    __syncthreads();

    float lsum[8], lsq[8];
    #pragma unroll
    for (int j = 0; j < 8; j++) { lsum[j] = 0.0f; lsq[j] = 0.0f; }
    #pragma unroll
    for (int mf = 0; mf < 4; mf++) {
        size_t r0 = m0 + wm0 + mf * 16 + rowq;
        size_t r1 = r0 + 8;
        float rs0 = g_rs[(int)(r0 % NJ)];
        float rs1 = g_rs[(int)(r1 % NJ)];
        bool v0 = r0 < MROWS, v1 = r1 < MROWS;
        #pragma unroll
        for (int nf = 0; nf < 4; nf++) {
            int c = n0 + wn0 + nf * 8 + colq;
            float b0 = g_bias[c], b1 = g_bias[c + 1];
            float x0 = fmaxf(acc[mf][nf][0] + rs0 * b0, 0.0f);
            float x1 = fmaxf(acc[mf][nf][1] + rs0 * b1, 0.0f);
            float x2 = fmaxf(acc[mf][nf][2] + rs1 * b0, 0.0f);
            float x3 = fmaxf(acc[mf][nf][3] + rs1 * b1, 0.0f);
            *(float2*)(g_h + r0 * DOUT + c) = make_float2(x0, x1);
            *(float2*)(g_h + r1 * DOUT + c) = make_float2(x2, x3);
            if (v0) {
                lsum[nf*2]   += x0; lsq[nf*2]   = fmaf(x0, x0, lsq[nf*2]);
                lsum[nf*2+1] += x1; lsq[nf*2+1] = fmaf(x1, x1, lsq[nf*2+1]);
            }
            if (v1) {
                lsum[nf*2]   += x2; lsq[nf*2]   = fmaf(x2, x2, lsq[nf*2]);
                lsum[nf*2+1] += x3; lsq[nf*2+1] = fmaf(x3, x3, lsq[nf*2+1]);
            }
        }
    }
    #pragma unroll
    for (int o = 4; o < 32; o <<= 1) {
        #pragma unroll
        for (int j = 0; j < 8; j++) {
            lsum[j] += __shfl_xor_sync(0xffffffffu, lsum[j], o);
            lsq[j]  += __shfl_xor_sync(0xffffffffu, lsq[j],  o);
        }
    }
    if (lane < 4) {
        #pragma unroll
        for (int nf = 0; nf < 4; nf++) {
            #pragma unroll
            for (int j = 0; j < 2; j++) {
                int cb = wn0 + nf * 8 + 2 * lane + j;
                atomicAdd(&sstat[cb],       lsum[nf*2 + j]);
                atomicAdd(&sstat[128 + cb], lsq[nf*2 + j]);
            }
        }
    }
    __syncthreads();
    if (tid < 128) atomicAdd(&g_bnsum[n0 + tid], sstat[tid]);
    else           atomicAdd(&g_bnsq [n0 + tid - 128], sstat[tid]);
}

// ---------------- BN finalize ----------------
__global__ void bnfin_kernel(const float* __restrict__ bng, const float* __restrict__ bnb) {
    int c = threadIdx.x;
    const float inv = 1.0f / (float)MROWS;
    float mean = g_bnsum[c] * inv;
    float var  = g_bnsq[c] * inv - mean * mean;
    float sc   = bng[c] * rsqrtf(var + EPSV);
    g_scale[c] = sc;
    g_shift[c] = bnb[c] - mean * sc;
}

// ---------------- fused BN + LayerNorm: fp32 h -> fp16 hn ----------------
__global__ void bnln_kernel(const float* __restrict__ lng, const float* __restrict__ lnb) {
    int warp = threadIdx.x >> 5, lane = threadIdx.x & 31;
    size_t row = (size_t)blockIdx.x * 8 + warp;
    int c0 = lane * 8;

    const float* hr = g_h + row * DOUT + c0;
    float4 v0 = *(const float4*)(hr);
    float4 v1 = *(const float4*)(hr + 4);
    float vin[8] = {v0.x, v0.y, v0.z, v0.w, v1.x, v1.y, v1.z, v1.w};

    float vals[8];
    float s = 0.0f, sq = 0.0f;
    #pragma unroll
    for (int j = 0; j < 8; j++) {
        float a = fmaf(vin[j], g_scale[c0 + j], g_shift[c0 + j]);
        vals[j] = a;
        s += a;
        sq = fmaf(a, a, sq);
    }
    #pragma unroll
    for (int o = 16; o > 0; o >>= 1) {
        s  += __shfl_xor_sync(0xffffffffu, s,  o);
        sq += __shfl_xor_sync(0xffffffffu, sq, o);
    }
    float mu  = s * (1.0f / DOUT);
    float var = sq * (1.0f / DOUT) - mu * mu;
    float inv = rsqrtf(var + EPSV);

    uint4 w;
    uint32_t* wp = (uint32_t*)&w;
    #pragma unroll
    for (int j = 0; j < 4; j++) {
        float a0 = fmaf((vals[2*j]   - mu) * inv, lng[c0 + 2*j],   lnb[c0 + 2*j]);
        float a1 = fmaf((vals[2*j+1] - mu) * inv, lng[c0 + 2*j+1], lnb[c0 + 2*j+1]);
        wp[j] = pack_half2(a0, a1);
    }
    *(uint4*)(g_hnh + row * DOUT + c0) = w;
}

// ---------------- fused GEMM2+GEMM3: mid stays in shared memory ----------------
// Grid = MTILES, 256 threads, 1 CTA/SM. smem 224 KB:
//   [0,64K)        A_hn tile: 128 x 256 fp16, 512B rows, swizzled
//   [64K,192K)     MID tile:  128 x 512 fp16, 1024B rows, swizzled
//   [192K,224K)    B staging: 2 x 16 KB double buffer
// Phase A: MID = relu(A_hn @ mw1^T + b1)   (4 n-chunks x 4 k-chunks)
// Phase B: out = MID @ mw2^T + b2          (2 n-chunks x 8 k-chunks)
__global__ void __launch_bounds__(256, 1)
gemm23_fused(const float* __restrict__ b1x, const float* __restrict__ b2x,
             float* __restrict__ Cout) {
    extern __shared__ char smem[];
    const uint32_t sb = smem_u32(smem);
    constexpr uint32_t MIDOF = 65536;
    constexpr uint32_t BST   = 196608;

    int tid = threadIdx.x;
    int wid = tid >> 5, lane = tid & 31;
    int wm0 = (wid & 1) * 64;
    int wn0 = (wid >> 1) * 32;
    size_t m0 = (size_t)blockIdx.x * 128;

    int srr = tid >> 3, scc = tid & 7;

    // frag addressing
    int la = lane & 15, lb = lane >> 4;
    int swA = la & 7;
    uint32_t browB = (uint32_t)(wn0 + (lane & 7) + ((lane >> 4) << 3));
    int bCk = (lane >> 3) & 1;
    int swB = lane & 7;
    int colq = 2 * (lane & 3);
    int rowq = lane >> 2;

    // stage mw1 chunk i=(nc,kc) into buffer buf
    auto stageA = [&](int i, int buf) {
        int nc = i >> 2, kc = i & 3;
        uint32_t bb = BST + (uint32_t)buf * 16384u;
        #pragma unroll
        for (int q = 0; q < 4; q++) {
            int r = srr + q * 32;
            size_t go = (size_t)(nc * 128 + r) * DOUT + kc * 64 + scc * 8;
            uint32_t so = bb + (uint32_t)(r * 128 + ((scc ^ (r & 7)) << 4));
            cpa16(sb + so, g_mw1h + go);
        }
    };
    // stage mw2 chunk j=(nb,kc) into buffer buf
    auto stageB2 = [&](int j, int buf) {
        int nb = j >> 3, kc = j & 7;
        uint32_t bb = BST + (uint32_t)buf * 16384u;
        #pragma unroll
        for (int q = 0; q < 4; q++) {
            int r = srr + q * 32;
            size_t go = (size_t)(nb * 128 + r) * DMID + kc * 64 + scc * 8;
            uint32_t so = bb + (uint32_t)(r * 128 + ((scc ^ (r & 7)) << 4));
            cpa16(sb + so, g_mw2h + go);
        }
    };

    // prologue: A_hn tile (64 KB) + first phase-A B chunk, one group
    #pragma unroll
    for (int q = 0; q < 16; q++) {
        int id = q * 256 + tid;
        int r = id >> 5, c = id & 31;
        size_t go = (m0 + r) * (size_t)DOUT + c * 8;
        uint32_t so = (uint32_t)(r * 512 + (((c & 24) | ((c ^ r) & 7)) << 4));
        cpa16(sb + so, g_hnh + go);
    }
    stageA(0, 0);
    CP_COMMIT();

    float acc[4][4][4];

    // ---------------- phase A ----------------
    for (int i = 0; i < 16; i++) {
        int nc = i >> 2, kc = i & 3;
        if (kc == 0) {
            #pragma unroll
            for (int mf = 0; mf < 4; mf++)
                #pragma unroll
                for (int nf = 0; nf < 4; nf++)
                    #pragma unroll
                    for (int e = 0; e < 4; e++) acc[mf][nf][e] = 0.0f;
        }
        CP_WAIT0();
        __syncthreads();
        if (i < 15) { stageA(i + 1, (i + 1) & 1); CP_COMMIT(); }
        else        { stageB2(0, 0);              CP_COMMIT(); }

        uint32_t bb = sb + BST + (uint32_t)(i & 1) * 16384u;
        #pragma unroll
        for (int ks = 0; ks < 4; ks++) {
            int gc = kc * 8 + ks * 2 + lb;              // A chunk 0..31
            int cb = ks * 2 + bCk;
            uint32_t choA = (uint32_t)(((gc & 24) | ((gc ^ swA) & 7)) << 4);
            uint32_t choB = (uint32_t)((cb ^ swB) << 4);
            uint32_t ah[4][4], bh0[4], bh1[4];
            #pragma unroll
            for (int mf = 0; mf < 4; mf++)
                ldsm4(ah[mf], sb + (uint32_t)(wm0 + la + mf * 16) * 512u + choA);
            ldsm4(bh0, bb + browB * 128u + choB);
            ldsm4(bh1, bb + browB * 128u + 2048u + choB);
            #pragma unroll
            for (int mf = 0; mf < 4; mf++) {
                #pragma unroll
                for (int nf = 0; nf < 4; nf++) {
                    const uint32_t* BHf = (nf < 2) ? bh0 : bh1;
                    uint32_t b0 = BHf[(nf & 1) * 2], b1 = BHf[(nf & 1) * 2 + 1];
                    mma_fp(acc[mf][nf], ah[mf], b0, b1);
                }
            }
        }

        if (kc == 3) {
            // epilogue: bias + relu -> MID (fp16, swizzled 1024B rows)
            #pragma unroll
            for (int mf = 0; mf < 4; mf++) {
                uint32_t r0 = (uint32_t)(wm0 + mf * 16 + rowq);
                uint32_t r1 = r0 + 8;
                #pragma unroll
                for (int nf = 0; nf < 4; nf++) {
                    int col = nc * 128 + wn0 + nf * 8 + colq;
                    float c0b = b1x[col], c1b = b1x[col + 1];
                    float x0 = fmaxf(acc[mf][nf][0] + c0b, 0.0f);
                    float x1 = fmaxf(acc[mf][nf][1] + c1b, 0.0f);
                    float x2 = fmaxf(acc[mf][nf][2] + c0b, 0.0f);
                    float x3 = fmaxf(acc[mf][nf][3] + c1b, 0.0f);
                    uint32_t ch = (uint32_t)col >> 3;
                    uint32_t lo = ((uint32_t)col & 7u) * 2u;
                    uint32_t so0 = MIDOF + r0 * 1024u + (((ch & 56u) | ((ch ^ (r0 & 7u)) & 7u)) << 4) + lo;
                    uint32_t so1 = MIDOF + r1 * 1024u + (((ch & 56u) | ((ch ^ (r1 & 7u)) & 7u)) << 4) + lo;
                    *(uint32_t*)(smem + so0) = pack_half2(x0, x1);
                    *(uint32_t*)(smem + so1) = pack_half2(x2, x3);
                }
            }
        }
    }

    // ---------------- phase B ----------------
    for (int j = 0; j < 16; j++) {
        int nb = j >> 3, kc = j & 7;
        if (kc == 0) {
            #pragma unroll
            for (int mf = 0; mf < 4; mf++)
                #pragma unroll
                for (int nf = 0; nf < 4; nf++)
                    #pragma unroll
                    for (int e = 0; e < 4; e++) acc[mf][nf][e] = 0.0f;
        }
        CP_WAIT0();
        __syncthreads();    // at j==0 this also publishes all MID writes
        if (j < 15) { stageB2(j + 1, (j + 1) & 1); CP_COMMIT(); }

        uint32_t bb = sb + BST + (uint32_t)(j & 1) * 16384u;
        #pragma unroll
        for (int ks = 0; ks < 4; ks++) {
            int gc = kc * 8 + ks * 2 + lb;              // MID chunk 0..63
            int cb = ks * 2 + bCk;
            uint32_t choA = (uint32_t)(((gc & 56) | ((gc ^ swA) & 7)) << 4);
            uint32_t choB = (uint32_t)((cb ^ swB) << 4);
            uint32_t ah[4][4], bh0[4], bh1[4];
            #pragma unroll
            for (int mf = 0; mf < 4; mf++)
                ldsm4(ah[mf], sb + MIDOF + (uint32_t)(wm0 + la + mf * 16) * 1024u + choA);
            ldsm4(bh0, bb + browB * 128u + choB);
            ldsm4(bh1, bb + browB * 128u + 2048u + choB);
            #pragma unroll
            for (int mf = 0; mf < 4; mf++) {
                #pragma unroll
                for (int nf = 0; nf < 4; nf++) {
                    const uint32_t* BHf = (nf < 2) ? bh0 : bh1;
                    uint32_t b0 = BHf[(nf & 1) * 2], b1 = BHf[(nf & 1) * 2 + 1];
                    mma_fp(acc[mf][nf], ah[mf], b0, b1);
                }
            }
        }

        if (kc == 7) {
            // epilogue: bias -> fp32 out (row-guarded)
            #pragma unroll
            for (int mf = 0; mf < 4; mf++) {
                size_t r0 = m0 + wm0 + mf * 16 + rowq;
                size_t r1 = r0 + 8;
                #pragma unroll
                for (int nf = 0; nf < 4; nf++) {
                    int c = nb * 128 + wn0 + nf * 8 + colq;
                    float c0b = b2x[c], c1b = b2x[c + 1];
                    if (r0 < MROWS)
                        *(float2*)(Cout + r0 * DOUT + c) =
                            make_float2(acc[mf][nf][0] + c0b, acc[mf][nf][1] + c1b);
                    if (r1 < MROWS)
                        *(float2*)(Cout + r1 * DOUT + c) =
                            make_float2(acc[mf][nf][2] + c0b, acc[mf][nf][3] + c1b);
                }
            }
        }
    }
}

// ---------------------------------------------------------------------------
extern "C" void kernel_launch(void* const* d_in, const int* in_sizes, int n_in,
                              void* d_out, int out_size) {
    const float* x   = (const float*)d_in[0];
    const float* adj = (const float*)d_in[1];
    const float* w1  = (const float*)d_in[2];
    const float* b1  = (const float*)d_in[3];
    const float* w2  = (const float*)d_in[4];
    const float* b2  = (const float*)d_in[5];
    const float* bng = (const float*)d_in[6];
    const float* bnb = (const float*)d_in[7];
    const float* lng = (const float*)d_in[8];
    const float* lnb = (const float*)d_in[9];
    const float* mw1 = (const float*)d_in[10];
    const float* mb1 = (const float*)d_in[11];
    const float* mw2 = (const float*)d_in[12];
    const float* mb2 = (const float*)d_in[13];
    float* out = (float*)d_out;

    const int SMEMH = 32768;    // GEMM1
    const int SMEMF = 229376;   // fused GEMM2+3: 224 KB (opt-in)

    // host-side config, not an allocation; idempotent, capture-safe
    cudaFuncSetAttribute(gemm23_fused, cudaFuncAttributeMaxDynamicSharedMemorySize, SMEMF);

    prep_kernel<<<1280, 256>>>(w1, b1, w2, b2, adj, mw1, mw2);
    agg_kernel<<<NSAMP, 256>>>(x, adj);
    // GEMM1: h(fp32) = relu(xa @ (w1+w2)^T + rs*bias), fused BN stats
    mma_gemm1<<<dim3(2, MTILES), 256, SMEMH>>>();
    bnfin_kernel<<<1, DOUT>>>(bng, bnb);
    bnln_kernel<<<MROWS / 8, 256>>>(lng, lnb);
    // fused MLP: out = (relu(hn @ mw1^T + b1)) @ mw2^T + b2, mid in smem
    gemm23_fused<<<MTILES, 256, SMEMF>>>(mb1, mb2, out);
}

// round 16
// speedup vs baseline: 1.3216x; 1.2617x over previous
#include <cuda_runtime.h>
#include <cuda_fp16.h>
#include <cstdint>

// ---------------- problem constants ----------------
#define NSAMP  15552
#define NJ     17
#define MROWS  (NSAMP*NJ)        // 264384
#define MTILES 2066              // ceil(MROWS/128)
#define MPAD   (MTILES*128)      // 264448
#define DIN    256
#define DOUT   256
#define DMID   512
#define EPSV   1e-5f

// ---------------- scratch (device globals; no runtime alloc) ----------------
static __device__ __half g_xah [(size_t)MPAD * DIN];
static __device__ __half g_hh  [(size_t)MPAD * DOUT];    // post-GCN relu h (fp16)

static __device__ __half g_wh  [DOUT * DIN];
static __device__ __half g_mw1h[DMID * DOUT];
static __device__ __half g_mw2h[DOUT * DMID];

static __device__ float g_bias [DOUT];
static __device__ float g_rs   [NJ];
static __device__ float g_bnsum[DOUT];
static __device__ float g_bnsq [DOUT];
static __device__ float g_scale[DOUT];
static __device__ float g_shift[DOUT];

// ---------------- helpers ----------------
__device__ __forceinline__ uint32_t smem_u32(const void* p) {
    uint32_t a;
    asm("{ .reg .u64 t; cvta.to.shared.u64 t, %1; cvt.u32.u64 %0, t; }" : "=r"(a) : "l"(p));
    return a;
}
__device__ __forceinline__ void ldsm4(uint32_t* r, uint32_t addr) {
    asm volatile("ldmatrix.sync.aligned.m8n8.x4.shared.b16 {%0,%1,%2,%3}, [%4];"
                 : "=r"(r[0]), "=r"(r[1]), "=r"(r[2]), "=r"(r[3]) : "r"(addr));
}
__device__ __forceinline__ void mma_fp(float* c, const uint32_t* a, uint32_t b0, uint32_t b1) {
    asm volatile("mma.sync.aligned.m16n8k16.row.col.f32.f16.f16.f32 "
                 "{%0,%1,%2,%3}, {%4,%5,%6,%7}, {%8,%9}, {%0,%1,%2,%3};"
                 : "+f"(c[0]), "+f"(c[1]), "+f"(c[2]), "+f"(c[3])
                 : "r"(a[0]), "r"(a[1]), "r"(a[2]), "r"(a[3]), "r"(b0), "r"(b1));
}
__device__ __forceinline__ void cpa16(uint32_t dst, const void* src) {
    asm volatile("cp.async.cg.shared.global [%0], [%1], 16;" :: "r"(dst), "l"(src));
}
#define CP_COMMIT() asm volatile("cp.async.commit_group;" ::: "memory")
#define CP_WAIT0()  asm volatile("cp.async.wait_group 0;" ::: "memory")

__device__ __forceinline__ uint32_t pack_half2(float a, float b) {
    __half2 h = __floats2half2_rn(a, b);
    return *(uint32_t*)&h;
}

// ---------------- K0: prep ----------------
__global__ void prep_kernel(const float* __restrict__ w1, const float* __restrict__ b1,
                            const float* __restrict__ w2, const float* __restrict__ b2,
                            const float* __restrict__ adj,
                            const float* __restrict__ mw1, const float* __restrict__ mw2) {
    int bid = blockIdx.x, tid = threadIdx.x;
    if (bid < 256) {
        int i = bid * 256 + tid;
        g_wh[i] = __float2half_rn(w1[i] + w2[i]);
    } else if (bid < 768) {
        int i = (bid - 256) * 256 + tid;
        g_mw1h[i] = __float2half_rn(mw1[i]);
    } else {
        int i = (bid - 768) * 256 + tid;
        g_mw2h[i] = __float2half_rn(mw2[i]);
    }
    if (bid < 64) {
        // zero padded tail rows of xa
        size_t p = (size_t)MROWS * 256 + bid * 256 + tid;
        g_xah[p] = __float2half(0.0f);
    }
    if (bid == 0) {
        g_bias[tid]  = b1[tid] + b2[tid];
        g_bnsum[tid] = 0.0f;
        g_bnsq[tid]  = 0.0f;
        if (tid < NJ) {
            float s = 0.0f;
            #pragma unroll
            for (int j = 0; j < NJ; j++) s += adj[tid * NJ + j];
            g_rs[tid] = s;
        }
    }
}

// ---------------- K1: adjacency aggregation -> fp16 ----------------
__global__ void agg_kernel(const float* __restrict__ x, const float* __restrict__ adj) {
    __shared__ float sadj[NJ * NJ];
    int t = threadIdx.x;
    for (int i = t; i < NJ * NJ; i += 256) sadj[i] = adj[i];
    __syncthreads();
    size_t base = (size_t)blockIdx.x * NJ * DIN + t;
    const float* xs = x + base;
    float xv[NJ];
    #pragma unroll
    for (int j = 0; j < NJ; j++) xv[j] = xs[(size_t)j * DIN];
    #pragma unroll
    for (int i = 0; i < NJ; i++) {
        float a = 0.0f;
        #pragma unroll
        for (int j = 0; j < NJ; j++) a = fmaf(sadj[i * NJ + j], xv[j], a);
        g_xah[base + (size_t)i * DIN] = __float2half_rn(a);
    }
}

// ---------------- GEMM1: fp16 HMMA, h(fp16) + fused BN stats ----------------
// Block 128x128, BK=64, 8 warps (2M x 4N), warp tile 64x32. 32 KB smem.
// BN stats computed from fp32 accumulators (exact), h quantized on store.
__global__ void __launch_bounds__(256, 2)
mma_gemm1() {
    extern __shared__ char smem[];
    const uint32_t sb = smem_u32(smem);
    constexpr uint32_t BOF = 16384;
    constexpr int K = DIN;

    int tid = threadIdx.x;
    int wid = tid >> 5, lane = tid & 31;
    int wm0 = (wid & 1) * 64;
    int wn0 = (wid >> 1) * 32;

    size_t m0 = (size_t)blockIdx.y * 128;
    int    n0 = blockIdx.x * 128;

    float acc[4][4][4] = {};

    int la = lane & 15, lb = lane >> 4;
    int swA = la & 7;
    uint32_t aBase = sb + (uint32_t)(wm0 + la) * 128u;
    uint32_t browB = (uint32_t)(wn0 + (lane & 7) + ((lane >> 4) << 3));
    int bCk = (lane >> 3) & 1;
    int swB = lane & 7;
    uint32_t bBase = sb + BOF + browB * 128u;

    int srr = tid >> 3, scc = tid & 7;

    #pragma unroll
    for (int kc = 0; kc < K / 64; kc++) {
        #pragma unroll
        for (int q = 0; q < 4; q++) {
            int r = srr + q * 32;
            size_t goA = (m0 + r) * (size_t)K + kc * 64 + scc * 8;
            size_t goB = (size_t)(n0 + r) * K + kc * 64 + scc * 8;
            uint32_t so = (uint32_t)(r * 128 + ((scc ^ (r & 7)) << 4));
            cpa16(sb + so, g_xah + goA);
            cpa16(sb + BOF + so, g_wh + goB);
        }
        CP_COMMIT();
        CP_WAIT0();
        __syncthreads();

        #pragma unroll
        for (int ks = 0; ks < 4; ks++) {
            int ca = ks * 2 + lb;
            int cb = ks * 2 + bCk;
            uint32_t choA = (uint32_t)((ca ^ swA) << 4);
            uint32_t choB = (uint32_t)((cb ^ swB) << 4);
            uint32_t ah[4][4];
            uint32_t bh0[4], bh1[4];
            #pragma unroll
            for (int mf = 0; mf < 4; mf++)
                ldsm4(ah[mf], aBase + mf * 2048u + choA);
            ldsm4(bh0, bBase + choB);
            ldsm4(bh1, bBase + 2048u + choB);
            #pragma unroll
            for (int mf = 0; mf < 4; mf++) {
                #pragma unroll
                for (int nf = 0; nf < 4; nf++) {
                    const uint32_t* BHf = (nf < 2) ? bh0 : bh1;
                    uint32_t b0 = BHf[(nf & 1) * 2], b1 = BHf[(nf & 1) * 2 + 1];
                    mma_fp(acc[mf][nf], ah[mf], b0, b1);
                }
            }
        }
        __syncthreads();
    }

    int colq = 2 * (lane & 3);
    int rowq = lane >> 2;

    float* sstat = (float*)smem;
    sstat[tid] = 0.0f;
    __syncthreads();

    float lsum[8], lsq[8];
    #pragma unroll
    for (int j = 0; j < 8; j++) { lsum[j] = 0.0f; lsq[j] = 0.0f; }
    #pragma unroll
    for (int mf = 0; mf < 4; mf++) {
        size_t r0 = m0 + wm0 + mf * 16 + rowq;
        size_t r1 = r0 + 8;
        float rs0 = g_rs[(int)(r0 % NJ)];
        float rs1 = g_rs[(int)(r1 % NJ)];
        bool v0 = r0 < MROWS, v1 = r1 < MROWS;
        #pragma unroll
        for (int nf = 0; nf < 4; nf++) {
            int c = n0 + wn0 + nf * 8 + colq;
            float b0 = g_bias[c], b1 = g_bias[c + 1];
            float x0 = fmaxf(acc[mf][nf][0] + rs0 * b0, 0.0f);
            float x1 = fmaxf(acc[mf][nf][1] + rs0 * b1, 0.0f);
            float x2 = fmaxf(acc[mf][nf][2] + rs1 * b0, 0.0f);
            float x3 = fmaxf(acc[mf][nf][3] + rs1 * b1, 0.0f);
            *(uint32_t*)(g_hh + r0 * DOUT + c) = pack_half2(x0, x1);
            *(uint32_t*)(g_hh + r1 * DOUT + c) = pack_half2(x2, x3);
            if (v0) {
                lsum[nf*2]   += x0; lsq[nf*2]   = fmaf(x0, x0, lsq[nf*2]);
                lsum[nf*2+1] += x1; lsq[nf*2+1] = fmaf(x1, x1, lsq[nf*2+1]);
            }
            if (v1) {
                lsum[nf*2]   += x2; lsq[nf*2]   = fmaf(x2, x2, lsq[nf*2]);
                lsum[nf*2+1] += x3; lsq[nf*2+1] = fmaf(x3, x3, lsq[nf*2+1]);
            }
        }
    }
    #pragma unroll
    for (int o = 4; o < 32; o <<= 1) {
        #pragma unroll
        for (int j = 0; j < 8; j++) {
            lsum[j] += __shfl_xor_sync(0xffffffffu, lsum[j], o);
            lsq[j]  += __shfl_xor_sync(0xffffffffu, lsq[j],  o);
        }
    }
    if (lane < 4) {
        #pragma unroll
        for (int nf = 0; nf < 4; nf++) {
            #pragma unroll
            for (int j = 0; j < 2; j++) {
                int cb = wn0 + nf * 8 + 2 * lane + j;
                atomicAdd(&sstat[cb],       lsum[nf*2 + j]);
                atomicAdd(&sstat[128 + cb], lsq[nf*2 + j]);
            }
        }
    }
    __syncthreads();
    if (tid < 128) atomicAdd(&g_bnsum[n0 + tid], sstat[tid]);
    else           atomicAdd(&g_bnsq [n0 + tid - 128], sstat[tid]);
}

// ---------------- BN finalize ----------------
__global__ void bnfin_kernel(const float* __restrict__ bng, const float* __restrict__ bnb) {
    int c = threadIdx.x;
    const float inv = 1.0f / (float)MROWS;
    float mean = g_bnsum[c] * inv;
    float var  = g_bnsq[c] * inv - mean * mean;
    float sc   = bng[c] * rsqrtf(var + EPSV);
    g_scale[c] = sc;
    g_shift[c] = bnb[c] - mean * sc;
}

// ---------------- fused BN+LN + GEMM2 + GEMM3: mid stays in shared memory ----------------
// Grid = MTILES, 256 threads, 1 CTA/SM. smem 224 KB:
//   [0,64K)        A tile: 128 x 256 fp16 (h, then normalized hn in place)
//   [64K,192K)     MID tile: 128 x 512 fp16, 1024B rows, swizzled
//   [192K,224K)    B staging: 2 x 16 KB double buffer
// Prologue: load h tile once; BN scale/shift + per-row LayerNorm in smem.
// Phase A: MID = relu(hn @ mw1^T + b1). Phase B: out = MID @ mw2^T + b2.
__global__ void __launch_bounds__(256, 1)
gemm23_fused(const float* __restrict__ b1x, const float* __restrict__ b2x,
             const float* __restrict__ lng, const float* __restrict__ lnb,
             float* __restrict__ Cout) {
    extern __shared__ char smem[];
    const uint32_t sb = smem_u32(smem);
    constexpr uint32_t MIDOF = 65536;
    constexpr uint32_t BST   = 196608;

    int tid = threadIdx.x;
    int wid = tid >> 5, lane = tid & 31;
    int wm0 = (wid & 1) * 64;
    int wn0 = (wid >> 1) * 32;
    size_t m0 = (size_t)blockIdx.x * 128;

    int srr = tid >> 3, scc = tid & 7;

    // frag addressing
    int la = lane & 15, lb = lane >> 4;
    int swA = la & 7;
    uint32_t browB = (uint32_t)(wn0 + (lane & 7) + ((lane >> 4) << 3));
    int bCk = (lane >> 3) & 1;
    int swB = lane & 7;
    int colq = 2 * (lane & 3);
    int rowq = lane >> 2;

    auto stageA = [&](int i, int buf) {          // mw1 chunk i=(nc,kc)
        int nc = i >> 2, kc = i & 3;
        uint32_t bb = BST + (uint32_t)buf * 16384u;
        #pragma unroll
        for (int q = 0; q < 4; q++) {
            int r = srr + q * 32;
            size_t go = (size_t)(nc * 128 + r) * DOUT + kc * 64 + scc * 8;
            uint32_t so = bb + (uint32_t)(r * 128 + ((scc ^ (r & 7)) << 4));
            cpa16(sb + so, g_mw1h + go);
        }
    };
    auto stageB2 = [&](int j, int buf) {         // mw2 chunk j=(nb,kc)
        int nb = j >> 3, kc = j & 7;
        uint32_t bb = BST + (uint32_t)buf * 16384u;
        #pragma unroll
        for (int q = 0; q < 4; q++) {
            int r = srr + q * 32;
            size_t go = (size_t)(nb * 128 + r) * DMID + kc * 64 + scc * 8;
            uint32_t so = bb + (uint32_t)(r * 128 + ((scc ^ (r & 7)) << 4));
            cpa16(sb + so, g_mw2h + go);
        }
    };

    // ---- prologue 1: load h tile (128 x 256 fp16 = 64 KB, swizzled 512B rows)
    #pragma unroll
    for (int q = 0; q < 16; q++) {
        int id = q * 256 + tid;                  // 0..4095
        int r = id >> 5, c = id & 31;
        size_t go = (m0 + r) * (size_t)DOUT + c * 8;
        uint32_t so = (uint32_t)(r * 512 + (((c & 24) | ((c ^ r) & 7)) << 4));
        cpa16(sb + so, g_hh + go);
    }
    stageA(0, 0);
    CP_COMMIT();
    CP_WAIT0();
    __syncthreads();

    // ---- prologue 2: BN + LayerNorm in place (warp per row; lane owns chunk=lane)
    {
        float sc8[8], sh8[8], lg8[8], lb8[8];
        #pragma unroll
        for (int j = 0; j < 8; j++) {
            int ch = lane * 8 + j;
            sc8[j] = g_scale[ch]; sh8[j] = g_shift[ch];
            lg8[j] = lng[ch];     lb8[j] = lnb[ch];
        }
        for (int p = 0; p < 16; p++) {
            int row = p * 8 + wid;
            char* ap = smem + row * 512 + (((lane & 24) | ((lane ^ row) & 7)) << 4);
            uint4 v = *(uint4*)ap;
            __half2* hp = (__half2*)&v;
            float vals[8];
            float s = 0.0f, sq = 0.0f;
            #pragma unroll
            for (int j = 0; j < 4; j++) {
                float2 f = __half22float2(hp[j]);
                float a0 = fmaf(f.x, sc8[2*j],   sh8[2*j]);
                float a1 = fmaf(f.y, sc8[2*j+1], sh8[2*j+1]);
                vals[2*j] = a0; vals[2*j+1] = a1;
                s += a0 + a1;
                sq = fmaf(a0, a0, fmaf(a1, a1, sq));
            }
            #pragma unroll
            for (int o = 16; o > 0; o >>= 1) {
                s  += __shfl_xor_sync(0xffffffffu, s,  o);
                sq += __shfl_xor_sync(0xffffffffu, sq, o);
            }
            float mu  = s * (1.0f / DOUT);
            float var = sq * (1.0f / DOUT) - mu * mu;
            float inv = rsqrtf(var + EPSV);
            uint4 w;
            uint32_t* wp = (uint32_t*)&w;
            #pragma unroll
            for (int j = 0; j < 4; j++) {
                float a0 = fmaf((vals[2*j]   - mu) * inv, lg8[2*j],   lb8[2*j]);
                float a1 = fmaf((vals[2*j+1] - mu) * inv, lg8[2*j+1], lb8[2*j+1]);
                wp[j] = pack_half2(a0, a1);
            }
            *(uint4*)ap = w;
        }
    }
    __syncthreads();

    float acc[4][4][4];

    // ---------------- phase A: MID = relu(hn @ mw1^T + b1) ----------------
    for (int i = 0; i < 16; i++) {
        int nc = i >> 2, kc = i & 3;
        if (kc == 0) {
            #pragma unroll
            for (int mf = 0; mf < 4; mf++)
                #pragma unroll
                for (int nf = 0; nf < 4; nf++)
                    #pragma unroll
                    for (int e = 0; e < 4; e++) acc[mf][nf][e] = 0.0f;
        }
        if (i > 0) { CP_WAIT0(); __syncthreads(); }
        if (i < 15) { stageA(i + 1, (i + 1) & 1); CP_COMMIT(); }
        else        { stageB2(0, 0);              CP_COMMIT(); }

        uint32_t bb = sb + BST + (uint32_t)(i & 1) * 16384u;
        #pragma unroll
        for (int ks = 0; ks < 4; ks++) {
            int gc = kc * 8 + ks * 2 + lb;
            int cb = ks * 2 + bCk;
            uint32_t choA = (uint32_t)(((gc & 24) | ((gc ^ swA) & 7)) << 4);
            uint32_t choB = (uint32_t)((cb ^ swB) << 4);
            uint32_t ah[4][4], bh0[4], bh1[4];
            #pragma unroll
            for (int mf = 0; mf < 4; mf++)
                ldsm4(ah[mf], sb + (uint32_t)(wm0 + la + mf * 16) * 512u + choA);
            ldsm4(bh0, bb + browB * 128u + choB);
            ldsm4(bh1, bb + browB * 128u + 2048u + choB);
            #pragma unroll
            for (int mf = 0; mf < 4; mf++) {
                #pragma unroll
                for (int nf = 0; nf < 4; nf++) {
                    const uint32_t* BHf = (nf < 2) ? bh0 : bh1;
                    uint32_t b0 = BHf[(nf & 1) * 2], b1 = BHf[(nf & 1) * 2 + 1];
                    mma_fp(acc[mf][nf], ah[mf], b0, b1);
                }
            }
        }

        if (kc == 3) {
            #pragma unroll
            for (int mf = 0; mf < 4; mf++) {
                uint32_t r0 = (uint32_t)(wm0 + mf * 16 + rowq);
                uint32_t r1 = r0 + 8;
                #pragma unroll
                for (int nf = 0; nf < 4; nf++) {
                    int col = nc * 128 + wn0 + nf * 8 + colq;
                    float c0b = b1x[col], c1b = b1x[col + 1];
                    float x0 = fmaxf(acc[mf][nf][0] + c0b, 0.0f);
                    float x1 = fmaxf(acc[mf][nf][1] + c1b, 0.0f);
                    float x2 = fmaxf(acc[mf][nf][2] + c0b, 0.0f);
                    float x3 = fmaxf(acc[mf][nf][3] + c1b, 0.0f);
                    uint32_t ch = (uint32_t)col >> 3;
                    uint32_t lo = ((uint32_t)col & 7u) * 2u;
                    uint32_t so0 = MIDOF + r0 * 1024u + (((ch & 56u) | ((ch ^ (r0 & 7u)) & 7u)) << 4) + lo;
                    uint32_t so1 = MIDOF + r1 * 1024u + (((ch & 56u) | ((ch ^ (r1 & 7u)) & 7u)) << 4) + lo;
                    *(uint32_t*)(smem + so0) = pack_half2(x0, x1);
                    *(uint32_t*)(smem + so1) = pack_half2(x2, x3);
                }
            }
        }
    }

    // ---------------- phase B: out = MID @ mw2^T + b2 ----------------
    for (int j = 0; j < 16; j++) {
        int nb = j >> 3, kc = j & 7;
        if (kc == 0) {
            #pragma unroll
            for (int mf = 0; mf < 4; mf++)
                #pragma unroll
                for (int nf = 0; nf < 4; nf++)
                    #pragma unroll
                    for (int e = 0; e < 4; e++) acc[mf][nf][e] = 0.0f;
        }
        CP_WAIT0();
        __syncthreads();    // at j==0 also publishes MID writes
        if (j < 15) { stageB2(j + 1, (j + 1) & 1); CP_COMMIT(); }

        uint32_t bb = sb + BST + (uint32_t)(j & 1) * 16384u;
        #pragma unroll
        for (int ks = 0; ks < 4; ks++) {
            int gc = kc * 8 + ks * 2 + lb;
            int cb = ks * 2 + bCk;
            uint32_t choA = (uint32_t)(((gc & 56) | ((gc ^ swA) & 7)) << 4);
            uint32_t choB = (uint32_t)((cb ^ swB) << 4);
            uint32_t ah[4][4], bh0[4], bh1[4];
            #pragma unroll
            for (int mf = 0; mf < 4; mf++)
                ldsm4(ah[mf], sb + MIDOF + (uint32_t)(wm0 + la + mf * 16) * 1024u + choA);
            ldsm4(bh0, bb + browB * 128u + choB);
            ldsm4(bh1, bb + browB * 128u + 2048u + choB);
            #pragma unroll
            for (int mf = 0; mf < 4; mf++) {
                #pragma unroll
                for (int nf = 0; nf < 4; nf++) {
                    const uint32_t* BHf = (nf < 2) ? bh0 : bh1;
                    uint32_t b0 = BHf[(nf & 1) * 2], b1 = BHf[(nf & 1) * 2 + 1];
                    mma_fp(acc[mf][nf], ah[mf], b0, b1);
                }
            }
        }

        if (kc == 7) {
            #pragma unroll
            for (int mf = 0; mf < 4; mf++) {
                size_t r0 = m0 + wm0 + mf * 16 + rowq;
                size_t r1 = r0 + 8;
                #pragma unroll
                for (int nf = 0; nf < 4; nf++) {
                    int c = nb * 128 + wn0 + nf * 8 + colq;
                    float c0b = b2x[c], c1b = b2x[c + 1];
                    if (r0 < MROWS)
                        *(float2*)(Cout + r0 * DOUT + c) =
                            make_float2(acc[mf][nf][0] + c0b, acc[mf][nf][1] + c1b);
                    if (r1 < MROWS)
                        *(float2*)(Cout + r1 * DOUT + c) =
                            make_float2(acc[mf][nf][2] + c0b, acc[mf][nf][3] + c1b);
                }
            }
        }
    }
}

// ---------------------------------------------------------------------------
extern "C" void kernel_launch(void* const* d_in, const int* in_sizes, int n_in,
                              void* d_out, int out_size) {
    const float* x   = (const float*)d_in[0];
    const float* adj = (const float*)d_in[1];
    const float* w1  = (const float*)d_in[2];
    const float* b1  = (const float*)d_in[3];
    const float* w2  = (const float*)d_in[4];
    const float* b2  = (const float*)d_in[5];
    const float* bng = (const float*)d_in[6];
    const float* bnb = (const float*)d_in[7];
    const float* lng = (const float*)d_in[8];
    const float* lnb = (const float*)d_in[9];
    const float* mw1 = (const float*)d_in[10];
    const float* mb1 = (const float*)d_in[11];
    const float* mw2 = (const float*)d_in[12];
    const float* mb2 = (const float*)d_in[13];
    float* out = (float*)d_out;

    const int SMEMH = 32768;    // GEMM1
    const int SMEMF = 229376;   // fused BN+LN+GEMM2+3: 224 KB (opt-in)

    // host-side config, not an allocation; idempotent, capture-safe
    cudaFuncSetAttribute(gemm23_fused, cudaFuncAttributeMaxDynamicSharedMemorySize, SMEMF);

    prep_kernel<<<1280, 256>>>(w1, b1, w2, b2, adj, mw1, mw2);
    agg_kernel<<<NSAMP, 256>>>(x, adj);
    // GEMM1: h(fp16) = relu(xa @ (w1+w2)^T + rs*bias), fused BN stats (exact)
    mma_gemm1<<<dim3(2, MTILES), 256, SMEMH>>>();
    bnfin_kernel<<<1, DOUT>>>(bng, bnb);
    // fused: out = (relu(LN(BN(h)) @ mw1^T + b1)) @ mw2^T + b2, mid in smem
    gemm23_fused<<<MTILES, 256, SMEMF>>>(mb1, mb2, lng, lnb, out);
}